// round 14
// baseline (speedup 1.0000x reference)
#include <cuda_runtime.h>
#include <math.h>
#include <stdint.h>

// Problem dims
#define BDIM 32    // batch
#define TDIM 64    // seq len
#define DDIM 32    // n vars / heads
#define HDIM 256   // hidden
#define ZDIM 64    // latent
#define G3   768   // 3*H

typedef unsigned long long ull;

// ---- scratch (static device arrays; no allocation) ----
__device__ float  g_encGi[BDIM * TDIM * G3];            // [b][t][g]
__device__ float  g_h0[BDIM * HDIM];                    // [b][u]
__device__ float  g_hT[BDIM * HDIM];                    // [b][u]
__device__ float4 g_Drz[DDIM * 128 * 256];              // [d][k2][u]
__device__ float4 g_Dn4[DDIM * 64 * 256];               // [d][k4][u]
__device__ float4 g_Erz[128 * 256];
__device__ float4 g_En4[64 * 256];
__device__ float  g_Cr[DDIM * DDIM * 256];              // [d][i][u]
__device__ float  g_Cz[DDIM * DDIM * 256];
__device__ float  g_Cn[DDIM * DDIM * 256];
__device__ float  g_decGi[(size_t)DDIM * TDIM * G3 * BDIM];  // [d][t][g][b]

__device__ __forceinline__ float sigmoidf_(float x) {
    return __fdividef(1.0f, 1.0f + __expf(-x));
}
__device__ __forceinline__ float tanhf_(float x) {
    return 1.0f - __fdividef(2.0f, __expf(2.0f * x) + 1.0f);
}
__device__ __forceinline__ void ffma2(ull& d, ull a, ull b) {
    asm("fma.rn.f32x2 %0, %1, %2, %0;" : "+l"(d) : "l"(a), "l"(b));
}
__device__ __forceinline__ ull fadd2(ull a, ull b) {
    ull r; asm("add.rn.f32x2 %0, %1, %2;" : "=l"(r) : "l"(a), "l"(b)); return r;
}
__device__ __forceinline__ ull pk2(float x, float y) {
    ull r; asm("mov.b64 %0, {%1, %2};" : "=l"(r) : "f"(x), "f"(y)); return r;
}
__device__ __forceinline__ float2 upk2(ull v) {
    float2 r; asm("mov.b64 {%0, %1}, %2;" : "=f"(r.x), "=f"(r.y) : "l"(v)); return r;
}
__device__ __forceinline__ uint32_t s2u(const void* p) {
    uint32_t a;
    asm("{ .reg .u64 t; cvta.to.shared.u64 t, %1; cvt.u32.u64 %0, t; }" : "=r"(a) : "l"(p));
    return a;
}
__device__ __forceinline__ uint32_t mapa_(uint32_t laddr, uint32_t rank) {
    uint32_t r;
    asm("mapa.shared::cluster.u32 %0, %1, %2;" : "=r"(r) : "r"(laddr), "r"(rank));
    return r;
}
__device__ __forceinline__ void st_cl64(uint32_t addr, ull v) {
    asm volatile("st.shared::cluster.b64 [%0], %1;" :: "r"(addr), "l"(v) : "memory");
}
__device__ __forceinline__ void st_cl32(uint32_t addr, float v) {
    asm volatile("st.shared::cluster.b32 [%0], %1;" :: "r"(addr), "f"(v) : "memory");
}
__device__ __forceinline__ void cluster_sync_() {
    asm volatile("barrier.cluster.arrive.aligned;" ::: "memory");
    asm volatile("barrier.cluster.wait.aligned;" ::: "memory");
}
__device__ __forceinline__ uint32_t ctarank_() {
    uint32_t r; asm("mov.u32 %0, %%cluster_ctarank;" : "=r"(r)); return r;
}

// ============================================================
// origin #1: encgi (blk<2048) + encoder weight transpose (2048..2111)
// ============================================================
__global__ __launch_bounds__(256) void prep_enc(
    const float* __restrict__ xp, const float* __restrict__ Wih,
    const float* __restrict__ bih, const float* __restrict__ Whh_e)
{
    __shared__ float xs[DDIM];
    int blk = blockIdx.x;
    int tid = threadIdx.x;
    if (blk < 2048) {
        int bt = blk;
        if (tid < DDIM) xs[tid] = xp[bt * DDIM + tid];
        __syncthreads();
#pragma unroll
        for (int r = 0; r < 3; r++) {
            int g = tid + r * HDIM;
            const float4* w = (const float4*)(Wih + g * DDIM);
            float acc = bih[g];
#pragma unroll
            for (int i4 = 0; i4 < DDIM / 4; i4++) {
                float4 wv = w[i4];
                acc += wv.x * xs[i4 * 4 + 0] + wv.y * xs[i4 * 4 + 1] +
                       wv.z * xs[i4 * 4 + 2] + wv.w * xs[i4 * 4 + 3];
            }
            g_encGi[bt * G3 + g] = acc;
        }
    } else {
        int k4 = blk - 2048;
        int u = tid;
        int k = k4 * 4;
        float4 rr = *(const float4*)(Whh_e + (size_t)u * HDIM + k);
        float4 zz = *(const float4*)(Whh_e + (size_t)(u + 256) * HDIM + k);
        float4 nn = *(const float4*)(Whh_e + (size_t)(u + 512) * HDIM + k);
        g_Erz[(k4 * 2 + 0) * 256 + u] = make_float4(rr.x, zz.x, rr.y, zz.y);
        g_Erz[(k4 * 2 + 1) * 256 + u] = make_float4(rr.z, zz.z, rr.w, zz.w);
        g_En4[k4 * 256 + u] = nn;
    }
}

// ============================================================
// s2: decoder weight transpose (2048 blocks)
// ============================================================
__global__ __launch_bounds__(256) void prep_dtrans(const float* __restrict__ Whh_d)
{
    int q = blockIdx.x;
    int d = q >> 6, k4 = q & 63;
    int u = threadIdx.x;
    const float* Wd = Whh_d + (size_t)d * G3 * HDIM;
    int k = k4 * 4;
    float4 rr = *(const float4*)(Wd + (size_t)u * HDIM + k);
    float4 zz = *(const float4*)(Wd + (size_t)(u + 256) * HDIM + k);
    float4 nn = *(const float4*)(Wd + (size_t)(u + 512) * HDIM + k);
    g_Drz[((size_t)(d * 128 + k4 * 2 + 0)) * 256 + u] = make_float4(rr.x, zz.x, rr.y, zz.y);
    g_Drz[((size_t)(d * 128 + k4 * 2 + 1)) * 256 + u] = make_float4(rr.z, zz.z, rr.w, zz.w);
    g_Dn4[((size_t)(d * 64 + k4)) * 256 + u] = nn;
}

// ============================================================
// s1 #1: wcomb (pitch-258, conflict-free). 3072 blocks.
// ============================================================
__global__ __launch_bounds__(256) void prep_wcomb(
    const float* __restrict__ Win, const float* __restrict__ hWih)
{
    __shared__ __align__(16) float sbuf[40 * 258];
    int d  = blockIdx.x / 96;
    int gb = blockIdx.x % 96;
    int tid = threadIdx.x;
    float* win_s = sbuf;               // [32][258]
    float* wih_s = sbuf + 32 * 258;    // [8][258]
    const float* winp = Win + (size_t)d * DDIM * HDIM;
    for (int idx = tid; idx < DDIM * HDIM; idx += 256) {
        int i = idx >> 8, h = idx & 255;
        win_s[i * 258 + h] = winp[idx];
    }
    const float* wihp = hWih + ((size_t)d * G3 + gb * 8) * HDIM;
    for (int idx = tid; idx < 8 * HDIM; idx += 256) {
        int gg = idx >> 8, h = idx & 255;
        wih_s[gg * 258 + h] = wihp[idx];
    }
    __syncthreads();
    int gg = tid & 7, i = tid >> 3;
    const ull* wp = (const ull*)&win_s[i * 258];
    const ull* gp = (const ull*)&wih_s[gg * 258];
    ull acc = 0ull;
#pragma unroll 8
    for (int h2 = 0; h2 < HDIM / 2; h2++) ffma2(acc, wp[h2], gp[h2]);
    float2 a2 = upk2(acc);
    int g = gb * 8 + gg;
    int gate = g >> 8, uu = g & 255;
    float* dst = gate == 0 ? g_Cr : (gate == 1 ? g_Cz : g_Cn);
    dst[((size_t)d * DDIM + i) * 256 + uu] = a2.x + a2.y;
}

// ============================================================
// s1 #2: decoder input gates from precomputed Wcomb
// ============================================================
#define WS_PITCH 33
#define DIN_PITCH 36
#define PD_TOT (G3 * WS_PITCH * 4 + DDIM * DIN_PITCH * 4)
__global__ __launch_bounds__(256) void prep_decgi(
    const float* __restrict__ xp, const float* __restrict__ xc)
{
    extern __shared__ char smem_pd[];
    float* ws  = (float*)smem_pd;                       // [768][33]
    float* din = (float*)(smem_pd + G3 * WS_PITCH * 4); // [32][36]
    int d  = blockIdx.x >> 3;
    int tb = blockIdx.x & 7;
    int tid = threadIdx.x;

    for (int gate = 0; gate < 3; gate++) {
        const float* src = (gate == 0 ? g_Cr : gate == 1 ? g_Cz : g_Cn) + (size_t)d * DDIM * 256;
        for (int i = 0; i < DDIM; i++) {
            ws[(gate * 256 + tid) * WS_PITCH + i] = src[i * 256 + tid];
        }
    }
    __syncthreads();

    for (int tt = 0; tt < 8; tt++) {
        int t = tb * 8 + tt;
        {
            const float* src = (t == 0) ? (xp + (size_t)(TDIM - 1) * DDIM)
                                        : (xc + (size_t)(t - 1) * DDIM);
#pragma unroll
            for (int it = 0; it < 4; it++) {
                int j = it * 256 + tid;
                int b = j >> 5, i = j & 31;
                din[i * DIN_PITCH + b] = src[(size_t)b * TDIM * DDIM + i];
            }
        }
        __syncthreads();
        float* outp = g_decGi + ((size_t)(d * TDIM + t) * G3) * BDIM;
#pragma unroll 4
        for (int k = 0; k < 24; k++) {
            int j4 = k * 256 + tid;
            int g = j4 >> 3;
            int b4 = (j4 & 7) * 4;
            ull a01 = 0ull, a23 = 0ull;
            const float* wrow = ws + g * WS_PITCH;
#pragma unroll 8
            for (int i = 0; i < DDIM; i++) {
                float w = wrow[i];
                ull w2 = pk2(w, w);
                float4 dv = *(const float4*)&din[i * DIN_PITCH + b4];
                ffma2(a01, w2, pk2(dv.x, dv.y));
                ffma2(a23, w2, pk2(dv.z, dv.w));
            }
            float2 r01 = upk2(a01), r23 = upk2(a23);
            *(float4*)(outp + (size_t)g * BDIM + b4) = make_float4(r01.x, r01.y, r23.x, r23.y);
        }
        __syncthreads();
    }
}

// ============================================================
// origin #2: Encoder GRU (proven 225us). 8 clusters of 4 CTAs.
// ============================================================
#define ESM_WN  131072
#define ESM_H0  196608
#define ESM_H1  200704
#define ESM_TOT 204800
__global__ __launch_bounds__(256, 1) __cluster_dims__(4, 1, 1)
void enc_gru_cl(const float* __restrict__ bhh)
{
    extern __shared__ char smem_e[];
    float4* w_n  = (float4*)(smem_e + ESM_WN);
    float*  hbuf0 = (float*)(smem_e + ESM_H0);
    float*  hbuf1 = (float*)(smem_e + ESM_H1);
    const ull* w_rz_u = (const ull*)smem_e;
    float4* w_rz = (float4*)smem_e;
    int cid = blockIdx.x >> 2;
    uint32_t r = ctarank_();
    int b0 = cid * 4;
    int tid = threadIdx.x;
    int ul = tid >> 2, bg = tid & 3;
    int gr = (int)r * 64 + ul;

    for (int i = tid; i < 128 * 64; i += 256) {
        int k2 = i >> 6, uu = i & 63;
        w_rz[k2 * 64 + uu] = g_Erz[k2 * 256 + (int)r * 64 + uu];
    }
    for (int i = tid; i < 64 * 64; i += 256) {
        int k4 = i >> 6, uu = i & 63;
        w_n[k4 * 64 + uu] = g_En4[k4 * 256 + (int)r * 64 + uu];
    }
    for (int i = tid; i < 256 * 4; i += 256) hbuf0[i] = 0.0f;

    float bhr = bhh[gr], bhz = bhh[gr + HDIM], bhn = bhh[gr + 2 * HDIM];
    float h_old = 0.0f;

    uint32_t hoff0 = s2u(&hbuf0[gr * 4 + bg]);
    uint32_t ra0 = 0, ra1 = 0, ra2 = 0;
    {
        uint32_t tmp[3]; int nr = 0;
        for (uint32_t c = 0; c < 4; c++) if (c != r) tmp[nr++] = mapa_(hoff0, c);
        ra0 = tmp[0]; ra1 = tmp[1]; ra2 = tmp[2];
    }
    __syncthreads();

    int b = b0 + bg;
    int p = 0;
    for (int t = 0; t < TDIM; t++) {
        const float* hr = p ? hbuf1 : hbuf0;
        const float* gi = g_encGi + ((size_t)b * TDIM + t) * G3;
        float gR = gi[gr], gZ = gi[gr + 256], gN = gi[gr + 512];

        ull aRZ[4] = {0ull, 0ull, 0ull, 0ull};
        float aN0 = 0.f, aN1 = 0.f, aN2 = 0.f, aN3 = 0.f;
#pragma unroll 8
        for (int k4 = 0; k4 < 64; k4++) {
            const ull* rp = &w_rz_u[((2 * k4) * 64 + ul) * 2];
            ull rz0 = rp[0], rz1 = rp[1];
            const ull* rq = &w_rz_u[((2 * k4 + 1) * 64 + ul) * 2];
            ull rz2 = rq[0], rz3 = rq[1];
            float4 nn = w_n[k4 * 64 + ul];
            const float* hb = &hr[(k4 * 4) * 4 + bg];
            float h0 = hb[0], h1 = hb[4], h2 = hb[8], h3 = hb[12];
            ffma2(aRZ[0], rz0, pk2(h0, h0)); aN0 = fmaf(nn.x, h0, aN0);
            ffma2(aRZ[1], rz1, pk2(h1, h1)); aN1 = fmaf(nn.y, h1, aN1);
            ffma2(aRZ[2], rz2, pk2(h2, h2)); aN2 = fmaf(nn.z, h2, aN2);
            ffma2(aRZ[3], rz3, pk2(h3, h3)); aN3 = fmaf(nn.w, h3, aN3);
        }
        float2 srz = upk2(fadd2(fadd2(aRZ[0], aRZ[1]), fadd2(aRZ[2], aRZ[3])));
        float sN = (aN0 + aN1) + (aN2 + aN3);
        float rr = sigmoidf_(gR + bhr + srz.x);
        float uu = sigmoidf_(gZ + bhz + srz.y);
        float nn = tanhf_(gN + rr * (sN + bhn));
        float hnew = (1.0f - uu) * nn + uu * h_old;
        h_old = hnew;

        float* hw = p ? hbuf0 : hbuf1;
        uint32_t roff = p ? 0u : 4096u;
        hw[gr * 4 + bg] = hnew;
        st_cl32(ra0 + roff, hnew); st_cl32(ra1 + roff, hnew); st_cl32(ra2 + roff, hnew);
        cluster_sync_();
        p ^= 1;
    }
    {
        int bw = b0 + (int)r;
        g_hT[(size_t)bw * HDIM + tid] = hbuf0[tid * 4 + (int)r];
    }
}

// ============================================================
// origin #3: Encoder head: mu, logsigma, z, h0. grid=B (32).
// ============================================================
__global__ __launch_bounds__(256) void enc_head(
    const float* __restrict__ mu_w,  const float* __restrict__ mu_b,
    const float* __restrict__ ls_w,  const float* __restrict__ ls_b,
    const float* __restrict__ refc_w, const float* __restrict__ refc_b,
    const float* __restrict__ eps,   float* __restrict__ out)
{
    int b = blockIdx.x;
    int u = threadIdx.x;
    __shared__ float hT[HDIM];
    __shared__ float zv[ZDIM];
    hT[u] = g_hT[(size_t)b * HDIM + u];
    __syncthreads();
    if (u < ZDIM) {
        const float* mw = mu_w + u * HDIM;
        const float* lw = ls_w + u * HDIM;
        float am = mu_b[u], al = ls_b[u];
#pragma unroll 8
        for (int k = 0; k < HDIM; k++) { am += mw[k] * hT[k]; al += lw[k] * hT[k]; }
        out[BDIM * TDIM * DDIM + b * ZDIM + u] = am;
        out[BDIM * TDIM * DDIM + BDIM * ZDIM + b * ZDIM + u] = al;
        zv[u] = am + eps[b * ZDIM + u] * __expf(al);
    }
    __syncthreads();
    {
        float acc = refc_b[u];
        const float* rw = refc_w + u * ZDIM;
#pragma unroll 8
        for (int j = 0; j < ZDIM; j++) acc += rw[j] * zv[j];
        g_h0[(size_t)b * HDIM + u] = tanhf_(acc);
    }
}

// ============================================================
// Decoder GRU: 512 threads (4 warps/SMSP), 4 batches/thread.
// 32 clusters of 4 CTAs. Post-sync fc (tid<256), exact sigmoid.
// ============================================================
#define DSM_WN  131072
#define DSM_H   196608
#define DSM_FCW 229376
#define DSM_TOT 230400
__global__ __launch_bounds__(512, 1) __cluster_dims__(4, 1, 1)
void dec_gru_cl(
    const float* __restrict__ bih_all, const float* __restrict__ bhh_all,
    const float* __restrict__ fcw_all, const float* __restrict__ fcb_all,
    float* __restrict__ out)
{
    extern __shared__ char smem_d[];
    float4* w_rz = (float4*)smem_d;
    float4* w_n  = (float4*)(smem_d + DSM_WN);
    float*  h_s  = (float*)(smem_d + DSM_H);     // [256][32]
    float*  fcw_s= (float*)(smem_d + DSM_FCW);
    __shared__ float wsum[8][8];

    int d = blockIdx.x >> 2;
    uint32_t r = ctarank_();
    int tid = threadIdx.x;
    int ul = tid >> 3, bg = tid & 7;     // unit-local 0..63, batch-group 0..7 (4 batches)
    int gr = (int)r * 64 + ul;

    {
        const float4* src_rz = g_Drz + (size_t)d * 128 * 256;
        for (int i = tid; i < 128 * 64; i += 512) {
            int k2 = i >> 6, uu = i & 63;
            w_rz[k2 * 64 + uu] = src_rz[(size_t)k2 * 256 + (int)r * 64 + uu];
        }
        const float4* src_n = g_Dn4 + (size_t)d * 64 * 256;
        for (int i = tid; i < 64 * 64; i += 512) {
            int k4 = i >> 6, uu = i & 63;
            w_n[k4 * 64 + uu] = src_n[(size_t)k4 * 256 + (int)r * 64 + uu];
        }
        if (tid < 256) fcw_s[tid] = fcw_all[d * HDIM + tid];
        for (int i = tid; i < 256 * 32; i += 512) {
            int uu = i >> 5, bb = i & 31;
            h_s[uu * 32 + bb] = g_h0[(size_t)bb * HDIM + uu];
        }
    }
    const float* bih = bih_all + d * G3;
    const float* bhh = bhh_all + d * G3;
    float br  = bih[gr] + bhh[gr];
    float bz  = bih[gr + HDIM] + bhh[gr + HDIM];
    float bni = bih[gr + 2 * HDIM];
    float bnh = bhh[gr + 2 * HDIM];
    float fcb = fcb_all[d];

    float hold[4];
#pragma unroll
    for (int j = 0; j < 4; j++) hold[j] = g_h0[(size_t)(bg * 4 + j) * HDIM + gr];

    uint32_t hoff = s2u(&h_s[gr * 32 + bg * 4]);
    uint32_t ra0, ra1, ra2;
    {
        uint32_t tmp[3]; int nr = 0;
        for (uint32_t c = 0; c < 4; c++) if (c != r) tmp[nr++] = mapa_(hoff, c);
        ra0 = tmp[0]; ra1 = tmp[1]; ra2 = tmp[2];
    }
    __syncthreads();

    const float* gi_base = g_decGi + ((size_t)d * TDIM * G3) * BDIM + (size_t)gr * BDIM + bg * 4;

    for (int t = 0; t < TDIM; t++) {
        const float* gp = gi_base + (size_t)t * G3 * BDIM;
        float4 gR4 = *(const float4*)(gp);
        float4 gZ4 = *(const float4*)(gp + 256 * BDIM);
        float4 gN4 = *(const float4*)(gp + 512 * BDIM);

        ull aR[2] = {0,0}, aZ[2] = {0,0}, aN[2] = {0,0};
#pragma unroll 8
        for (int k4 = 0; k4 < 64; k4++) {
            float4 rzA = w_rz[(2 * k4) * 64 + ul];
            float4 rzB = w_rz[(2 * k4 + 1) * 64 + ul];
            float4 nn  = w_n[k4 * 64 + ul];
            ulonglong2 h0v = *(const ulonglong2*)&h_s[(k4 * 4 + 0) * 32 + bg * 4];
            ulonglong2 h1v = *(const ulonglong2*)&h_s[(k4 * 4 + 1) * 32 + bg * 4];
            ulonglong2 h2v = *(const ulonglong2*)&h_s[(k4 * 4 + 2) * 32 + bg * 4];
            ulonglong2 h3v = *(const ulonglong2*)&h_s[(k4 * 4 + 3) * 32 + bg * 4];
            {
                ull wr = pk2(rzA.x, rzA.x), wz = pk2(rzA.y, rzA.y), wn = pk2(nn.x, nn.x);
                ffma2(aR[0], wr, h0v.x); ffma2(aR[1], wr, h0v.y);
                ffma2(aZ[0], wz, h0v.x); ffma2(aZ[1], wz, h0v.y);
                ffma2(aN[0], wn, h0v.x); ffma2(aN[1], wn, h0v.y);
            }
            {
                ull wr = pk2(rzA.z, rzA.z), wz = pk2(rzA.w, rzA.w), wn = pk2(nn.y, nn.y);
                ffma2(aR[0], wr, h1v.x); ffma2(aR[1], wr, h1v.y);
                ffma2(aZ[0], wz, h1v.x); ffma2(aZ[1], wz, h1v.y);
                ffma2(aN[0], wn, h1v.x); ffma2(aN[1], wn, h1v.y);
            }
            {
                ull wr = pk2(rzB.x, rzB.x), wz = pk2(rzB.y, rzB.y), wn = pk2(nn.z, nn.z);
                ffma2(aR[0], wr, h2v.x); ffma2(aR[1], wr, h2v.y);
                ffma2(aZ[0], wz, h2v.x); ffma2(aZ[1], wz, h2v.y);
                ffma2(aN[0], wn, h2v.x); ffma2(aN[1], wn, h2v.y);
            }
            {
                ull wr = pk2(rzB.z, rzB.z), wz = pk2(rzB.w, rzB.w), wn = pk2(nn.w, nn.w);
                ffma2(aR[0], wr, h3v.x); ffma2(aR[1], wr, h3v.y);
                ffma2(aZ[0], wz, h3v.x); ffma2(aZ[1], wz, h3v.y);
                ffma2(aN[0], wn, h3v.x); ffma2(aN[1], wn, h3v.y);
            }
        }

        float gR[4] = {gR4.x, gR4.y, gR4.z, gR4.w};
        float gZ[4] = {gZ4.x, gZ4.y, gZ4.z, gZ4.w};
        float gN[4] = {gN4.x, gN4.y, gN4.z, gN4.w};
        float hn[4];
#pragma unroll
        for (int p = 0; p < 2; p++) {
            float2 sR = upk2(aR[p]), sZ = upk2(aZ[p]), sN = upk2(aN[p]);
            float rA = sigmoidf_(gR[2*p]   + br + sR.x);
            float rB = sigmoidf_(gR[2*p+1] + br + sR.y);
            float uA = sigmoidf_(gZ[2*p]   + bz + sZ.x);
            float uB = sigmoidf_(gZ[2*p+1] + bz + sZ.y);
            float nA = tanhf_(gN[2*p]   + bni + rA * (sN.x + bnh));
            float nB = tanhf_(gN[2*p+1] + bni + rB * (sN.y + bnh));
            hn[2*p]   = (1.0f - uA) * nA + uA * hold[2*p];
            hn[2*p+1] = (1.0f - uB) * nB + uB * hold[2*p+1];
        }
#pragma unroll
        for (int j = 0; j < 4; j++) hold[j] = hn[j];

        cluster_sync_();   // all reads of h_s done
        ull h01 = pk2(hn[0], hn[1]), h23 = pk2(hn[2], hn[3]);
        ull* lp = (ull*)&h_s[gr * 32 + bg * 4];
        lp[0] = h01; lp[1] = h23;
        st_cl64(ra0, h01); st_cl64(ra0 + 8, h23);
        st_cl64(ra1, h01); st_cl64(ra1 + 8, h23);
        st_cl64(ra2, h01); st_cl64(ra2 + 8, h23);
        cluster_sync_();   // h_new visible everywhere

        // fc output (threads 0..255 = one per unit)
        {
            float pr[8];
            if (tid < 256) {
                float4 ha = *(const float4*)&h_s[tid * 32 + (int)r * 8];
                float4 hb = *(const float4*)&h_s[tid * 32 + (int)r * 8 + 4];
                float fw = fcw_s[tid];
                pr[0] = fw * ha.x; pr[1] = fw * ha.y; pr[2] = fw * ha.z; pr[3] = fw * ha.w;
                pr[4] = fw * hb.x; pr[5] = fw * hb.y; pr[6] = fw * hb.z; pr[7] = fw * hb.w;
#pragma unroll
                for (int off = 16; off; off >>= 1) {
#pragma unroll
                    for (int bb = 0; bb < 8; bb++)
                        pr[bb] += __shfl_xor_sync(0xffffffff, pr[bb], off);
                }
                if ((tid & 31) == 0) {
                    int w = tid >> 5;
#pragma unroll
                    for (int bb = 0; bb < 8; bb++) wsum[w][bb] = pr[bb];
                }
            }
            __syncthreads();
            if (tid < 8) {
                float s = fcb;
#pragma unroll
                for (int w = 0; w < 8; w++) s += wsum[w][tid];
                int b = (int)r * 8 + tid;
                out[((size_t)b * TDIM + t) * DDIM + d] = s;
            }
        }
    }
}

// ============================================================
// launch — R7/R13 DAG
// ============================================================
extern "C" void kernel_launch(void* const* d_in, const int* in_sizes, int n_in,
                              void* d_out, int out_size)
{
    const float* x_past   = (const float*)d_in[0];
    const float* x_current= (const float*)d_in[1];
    const float* eps      = (const float*)d_in[2];
    const float* enc_Wih  = (const float*)d_in[3];
    const float* enc_bih  = (const float*)d_in[4];
    const float* enc_Whh  = (const float*)d_in[5];
    const float* enc_bhh  = (const float*)d_in[6];
    const float* enc_mu_w = (const float*)d_in[7];
    const float* enc_mu_b = (const float*)d_in[8];
    const float* enc_ls_w = (const float*)d_in[9];
    const float* enc_ls_b = (const float*)d_in[10];
    const float* refc_w   = (const float*)d_in[11];
    const float* refc_b   = (const float*)d_in[12];
    const float* Win      = (const float*)d_in[13];
    const float* h_Wih    = (const float*)d_in[14];
    const float* h_bih    = (const float*)d_in[15];
    const float* h_Whh    = (const float*)d_in[16];
    const float* h_bhh    = (const float*)d_in[17];
    const float* fc_w     = (const float*)d_in[18];
    const float* fc_b     = (const float*)d_in[19];
    float* out = (float*)d_out;

    static cudaStream_t s1 = nullptr, s2 = nullptr;
    static cudaEvent_t eF = nullptr, e1 = nullptr, e2 = nullptr;
    if (!s1) {
        cudaStreamCreateWithFlags(&s1, cudaStreamNonBlocking);
        cudaStreamCreateWithFlags(&s2, cudaStreamNonBlocking);
        cudaEventCreateWithFlags(&eF, cudaEventDisableTiming);
        cudaEventCreateWithFlags(&e1, cudaEventDisableTiming);
        cudaEventCreateWithFlags(&e2, cudaEventDisableTiming);
        cudaFuncSetAttribute(prep_decgi, cudaFuncAttributeMaxDynamicSharedMemorySize, PD_TOT);
        cudaFuncSetAttribute(enc_gru_cl, cudaFuncAttributeMaxDynamicSharedMemorySize, ESM_TOT);
        cudaFuncSetAttribute(dec_gru_cl, cudaFuncAttributeMaxDynamicSharedMemorySize, DSM_TOT);
    }

    // fork side streams off the capture-origin stream
    cudaEventRecord(eF, 0);
    cudaStreamWaitEvent(s1, eF, 0);
    cudaStreamWaitEvent(s2, eF, 0);

    // origin: encoder chain
    prep_enc<<<2112, 256>>>(x_past, enc_Wih, enc_bih, enc_Whh);          // #1
    // s1: decoder input-gate chain
    prep_wcomb<<<DDIM * 96, 256, 0, s1>>>(Win, h_Wih);                   // #2
    enc_gru_cl<<<32, 256, ESM_TOT>>>(enc_bhh);                           // #3
    prep_decgi<<<256, 256, PD_TOT, s1>>>(x_past, x_current);             // #4
    // s2: decoder weight transpose
    prep_dtrans<<<2048, 256, 0, s2>>>(h_Whh);                            // #5
    enc_head<<<BDIM, 256>>>(enc_mu_w, enc_mu_b, enc_ls_w, enc_ls_b,
                            refc_w, refc_b, eps, out);                   // #6

    // join
    cudaEventRecord(e1, s1);
    cudaEventRecord(e2, s2);
    cudaStreamWaitEvent(0, e1, 0);
    cudaStreamWaitEvent(0, e2, 0);
    dec_gru_cl<<<DDIM * 4, 512, DSM_TOT>>>(h_bih, h_bhh, fc_w, fc_b, out); // #7
}

// round 15
// speedup vs baseline: 1.1724x; 1.1724x over previous
#include <cuda_runtime.h>
#include <math.h>
#include <stdint.h>

// Problem dims
#define BDIM 32    // batch
#define TDIM 64    // seq len
#define DDIM 32    // n vars / heads
#define HDIM 256   // hidden
#define ZDIM 64    // latent
#define G3   768   // 3*H

typedef unsigned long long ull;

// ---- scratch (static device arrays; no allocation) ----
__device__ float  g_encGi[BDIM * TDIM * G3];            // [b][t][g]
__device__ float  g_h0[BDIM * HDIM];                    // [b][u]
__device__ float  g_hT[BDIM * HDIM];                    // [b][u]
__device__ float4 g_Drz[DDIM * 128 * 256];              // [d][k2][u]
__device__ float4 g_Dn4[DDIM * 64 * 256];               // [d][k4][u]
__device__ float4 g_Erz[128 * 256];
__device__ float4 g_En4[64 * 256];
__device__ float  g_Cr[DDIM * DDIM * 256];              // [d][i][u]
__device__ float  g_Cz[DDIM * DDIM * 256];
__device__ float  g_Cn[DDIM * DDIM * 256];
__device__ float  g_decGi[(size_t)DDIM * TDIM * G3 * BDIM];  // [d][t][g][b]

__device__ __forceinline__ float sigmoidf_(float x) {
    return __fdividef(1.0f, 1.0f + __expf(-x));
}
__device__ __forceinline__ float tanhf_(float x) {
    return 1.0f - __fdividef(2.0f, __expf(2.0f * x) + 1.0f);
}
__device__ __forceinline__ void ffma2(ull& d, ull a, ull b) {
    asm("fma.rn.f32x2 %0, %1, %2, %0;" : "+l"(d) : "l"(a), "l"(b));
}
__device__ __forceinline__ ull fadd2(ull a, ull b) {
    ull r; asm("add.rn.f32x2 %0, %1, %2;" : "=l"(r) : "l"(a), "l"(b)); return r;
}
__device__ __forceinline__ ull pk2(float x, float y) {
    ull r; asm("mov.b64 %0, {%1, %2};" : "=l"(r) : "f"(x), "f"(y)); return r;
}
__device__ __forceinline__ float2 upk2(ull v) {
    float2 r; asm("mov.b64 {%0, %1}, %2;" : "=f"(r.x), "=f"(r.y) : "l"(v)); return r;
}
__device__ __forceinline__ uint32_t s2u(const void* p) {
    uint32_t a;
    asm("{ .reg .u64 t; cvta.to.shared.u64 t, %1; cvt.u32.u64 %0, t; }" : "=r"(a) : "l"(p));
    return a;
}
__device__ __forceinline__ uint32_t mapa_(uint32_t laddr, uint32_t rank) {
    uint32_t r;
    asm("mapa.shared::cluster.u32 %0, %1, %2;" : "=r"(r) : "r"(laddr), "r"(rank));
    return r;
}
__device__ __forceinline__ void st_cl64(uint32_t addr, ull v) {
    asm volatile("st.shared::cluster.b64 [%0], %1;" :: "r"(addr), "l"(v) : "memory");
}
__device__ __forceinline__ void st_cl32(uint32_t addr, float v) {
    asm volatile("st.shared::cluster.b32 [%0], %1;" :: "r"(addr), "f"(v) : "memory");
}
__device__ __forceinline__ void cluster_sync_() {
    asm volatile("barrier.cluster.arrive.aligned;" ::: "memory");
    asm volatile("barrier.cluster.wait.aligned;" ::: "memory");
}
__device__ __forceinline__ uint32_t ctarank_() {
    uint32_t r; asm("mov.u32 %0, %%cluster_ctarank;" : "=r"(r)); return r;
}

// ============================================================
// origin #1: encgi (blk<2048) + encoder weight transpose (2048..2111)
// ============================================================
__global__ __launch_bounds__(256) void prep_enc(
    const float* __restrict__ xp, const float* __restrict__ Wih,
    const float* __restrict__ bih, const float* __restrict__ Whh_e)
{
    __shared__ float xs[DDIM];
    int blk = blockIdx.x;
    int tid = threadIdx.x;
    if (blk < 2048) {
        int bt = blk;
        if (tid < DDIM) xs[tid] = xp[bt * DDIM + tid];
        __syncthreads();
#pragma unroll
        for (int r = 0; r < 3; r++) {
            int g = tid + r * HDIM;
            const float4* w = (const float4*)(Wih + g * DDIM);
            float acc = bih[g];
#pragma unroll
            for (int i4 = 0; i4 < DDIM / 4; i4++) {
                float4 wv = w[i4];
                acc += wv.x * xs[i4 * 4 + 0] + wv.y * xs[i4 * 4 + 1] +
                       wv.z * xs[i4 * 4 + 2] + wv.w * xs[i4 * 4 + 3];
            }
            g_encGi[bt * G3 + g] = acc;
        }
    } else {
        int k4 = blk - 2048;
        int u = tid;
        int k = k4 * 4;
        float4 rr = *(const float4*)(Whh_e + (size_t)u * HDIM + k);
        float4 zz = *(const float4*)(Whh_e + (size_t)(u + 256) * HDIM + k);
        float4 nn = *(const float4*)(Whh_e + (size_t)(u + 512) * HDIM + k);
        g_Erz[(k4 * 2 + 0) * 256 + u] = make_float4(rr.x, zz.x, rr.y, zz.y);
        g_Erz[(k4 * 2 + 1) * 256 + u] = make_float4(rr.z, zz.z, rr.w, zz.w);
        g_En4[k4 * 256 + u] = nn;
    }
}

// ============================================================
// s2: decoder weight transpose (2048 blocks)
// ============================================================
__global__ __launch_bounds__(256) void prep_dtrans(const float* __restrict__ Whh_d)
{
    int q = blockIdx.x;
    int d = q >> 6, k4 = q & 63;
    int u = threadIdx.x;
    const float* Wd = Whh_d + (size_t)d * G3 * HDIM;
    int k = k4 * 4;
    float4 rr = *(const float4*)(Wd + (size_t)u * HDIM + k);
    float4 zz = *(const float4*)(Wd + (size_t)(u + 256) * HDIM + k);
    float4 nn = *(const float4*)(Wd + (size_t)(u + 512) * HDIM + k);
    g_Drz[((size_t)(d * 128 + k4 * 2 + 0)) * 256 + u] = make_float4(rr.x, zz.x, rr.y, zz.y);
    g_Drz[((size_t)(d * 128 + k4 * 2 + 1)) * 256 + u] = make_float4(rr.z, zz.z, rr.w, zz.w);
    g_Dn4[((size_t)(d * 64 + k4)) * 256 + u] = nn;
}

// ============================================================
// s1 #1: wcomb (pitch-258, conflict-free). 3072 blocks.
// ============================================================
__global__ __launch_bounds__(256) void prep_wcomb(
    const float* __restrict__ Win, const float* __restrict__ hWih)
{
    __shared__ __align__(16) float sbuf[40 * 258];
    int d  = blockIdx.x / 96;
    int gb = blockIdx.x % 96;
    int tid = threadIdx.x;
    float* win_s = sbuf;               // [32][258]
    float* wih_s = sbuf + 32 * 258;    // [8][258]
    const float* winp = Win + (size_t)d * DDIM * HDIM;
    for (int idx = tid; idx < DDIM * HDIM; idx += 256) {
        int i = idx >> 8, h = idx & 255;
        win_s[i * 258 + h] = winp[idx];
    }
    const float* wihp = hWih + ((size_t)d * G3 + gb * 8) * HDIM;
    for (int idx = tid; idx < 8 * HDIM; idx += 256) {
        int gg = idx >> 8, h = idx & 255;
        wih_s[gg * 258 + h] = wihp[idx];
    }
    __syncthreads();
    int gg = tid & 7, i = tid >> 3;
    const ull* wp = (const ull*)&win_s[i * 258];
    const ull* gp = (const ull*)&wih_s[gg * 258];
    ull acc = 0ull;
#pragma unroll 8
    for (int h2 = 0; h2 < HDIM / 2; h2++) ffma2(acc, wp[h2], gp[h2]);
    float2 a2 = upk2(acc);
    int g = gb * 8 + gg;
    int gate = g >> 8, uu = g & 255;
    float* dst = gate == 0 ? g_Cr : (gate == 1 ? g_Cz : g_Cn);
    dst[((size_t)d * DDIM + i) * 256 + uu] = a2.x + a2.y;
}

// ============================================================
// s1 #2 (REWRITTEN): decoder input gates.
// grid = d(32) x gate(3) x thalf(2) = 192 CTAs, 256 threads.
// Thread u owns gate-row g = gate*256+u: its 32 weights live in REGISTERS.
// din staged per step [32][34], read warp-broadcast (conflict-free).
// ============================================================
__global__ __launch_bounds__(256) void prep_decgi(
    const float* __restrict__ xp, const float* __restrict__ xc)
{
    __shared__ __align__(16) float din[DDIM * 34];   // 4.25 KB
    int bid = blockIdx.x;
    int d = bid / 6;
    int rem = bid % 6;
    int gate = rem >> 1;
    int th = rem & 1;
    int u = threadIdx.x;

    // weights -> registers (coalesced over u)
    const float* csrc = (gate == 0 ? g_Cr : gate == 1 ? g_Cz : g_Cn) + (size_t)d * DDIM * 256 + u;
    float wreg[DDIM];
#pragma unroll
    for (int i = 0; i < DDIM; i++) wreg[i] = csrc[i * 256];

    int g = gate * 256 + u;
    for (int t = th * 32; t < th * 32 + 32; t++) {
        // stage dec_in[:, t, :] transposed: din[i][b]
        {
            const float* src = (t == 0) ? (xp + (size_t)(TDIM - 1) * DDIM)
                                        : (xc + (size_t)(t - 1) * DDIM);
#pragma unroll
            for (int it = 0; it < 4; it++) {
                int j = it * 256 + u;
                int b = j >> 5, i = j & 31;
                din[i * 34 + b] = src[(size_t)b * TDIM * DDIM + i];
            }
        }
        __syncthreads();

        ull acc[16];
#pragma unroll
        for (int j = 0; j < 16; j++) acc[j] = 0ull;
#pragma unroll 8
        for (int i = 0; i < DDIM; i++) {
            float w = wreg[i];
            ull w2 = pk2(w, w);
            const ull* dp = (const ull*)&din[i * 34];   // 34 even -> 8B aligned
#pragma unroll
            for (int j = 0; j < 16; j++) ffma2(acc[j], w2, dp[j]);
        }
        float* outp = g_decGi + (((size_t)(d * TDIM + t)) * G3 + g) * BDIM;
#pragma unroll
        for (int j = 0; j < 8; j++) {
            float2 a = upk2(acc[2 * j]), b2 = upk2(acc[2 * j + 1]);
            *(float4*)(outp + j * 4) = make_float4(a.x, a.y, b2.x, b2.y);
        }
        __syncthreads();   // done reading din before next staging
    }
}

// ============================================================
// origin #2: Encoder GRU (proven 225us). 8 clusters of 4 CTAs.
// ============================================================
#define ESM_WN  131072
#define ESM_H0  196608
#define ESM_H1  200704
#define ESM_TOT 204800
__global__ __launch_bounds__(256, 1) __cluster_dims__(4, 1, 1)
void enc_gru_cl(const float* __restrict__ bhh)
{
    extern __shared__ char smem_e[];
    float4* w_n  = (float4*)(smem_e + ESM_WN);
    float*  hbuf0 = (float*)(smem_e + ESM_H0);
    float*  hbuf1 = (float*)(smem_e + ESM_H1);
    const ull* w_rz_u = (const ull*)smem_e;
    float4* w_rz = (float4*)smem_e;
    int cid = blockIdx.x >> 2;
    uint32_t r = ctarank_();
    int b0 = cid * 4;
    int tid = threadIdx.x;
    int ul = tid >> 2, bg = tid & 3;
    int gr = (int)r * 64 + ul;

    for (int i = tid; i < 128 * 64; i += 256) {
        int k2 = i >> 6, uu = i & 63;
        w_rz[k2 * 64 + uu] = g_Erz[k2 * 256 + (int)r * 64 + uu];
    }
    for (int i = tid; i < 64 * 64; i += 256) {
        int k4 = i >> 6, uu = i & 63;
        w_n[k4 * 64 + uu] = g_En4[k4 * 256 + (int)r * 64 + uu];
    }
    for (int i = tid; i < 256 * 4; i += 256) hbuf0[i] = 0.0f;

    float bhr = bhh[gr], bhz = bhh[gr + HDIM], bhn = bhh[gr + 2 * HDIM];
    float h_old = 0.0f;

    uint32_t hoff0 = s2u(&hbuf0[gr * 4 + bg]);
    uint32_t ra0 = 0, ra1 = 0, ra2 = 0;
    {
        uint32_t tmp[3]; int nr = 0;
        for (uint32_t c = 0; c < 4; c++) if (c != r) tmp[nr++] = mapa_(hoff0, c);
        ra0 = tmp[0]; ra1 = tmp[1]; ra2 = tmp[2];
    }
    __syncthreads();

    int b = b0 + bg;
    int p = 0;
    for (int t = 0; t < TDIM; t++) {
        const float* hr = p ? hbuf1 : hbuf0;
        const float* gi = g_encGi + ((size_t)b * TDIM + t) * G3;
        float gR = gi[gr], gZ = gi[gr + 256], gN = gi[gr + 512];

        ull aRZ[4] = {0ull, 0ull, 0ull, 0ull};
        float aN0 = 0.f, aN1 = 0.f, aN2 = 0.f, aN3 = 0.f;
#pragma unroll 8
        for (int k4 = 0; k4 < 64; k4++) {
            const ull* rp = &w_rz_u[((2 * k4) * 64 + ul) * 2];
            ull rz0 = rp[0], rz1 = rp[1];
            const ull* rq = &w_rz_u[((2 * k4 + 1) * 64 + ul) * 2];
            ull rz2 = rq[0], rz3 = rq[1];
            float4 nn = w_n[k4 * 64 + ul];
            const float* hb = &hr[(k4 * 4) * 4 + bg];
            float h0 = hb[0], h1 = hb[4], h2 = hb[8], h3 = hb[12];
            ffma2(aRZ[0], rz0, pk2(h0, h0)); aN0 = fmaf(nn.x, h0, aN0);
            ffma2(aRZ[1], rz1, pk2(h1, h1)); aN1 = fmaf(nn.y, h1, aN1);
            ffma2(aRZ[2], rz2, pk2(h2, h2)); aN2 = fmaf(nn.z, h2, aN2);
            ffma2(aRZ[3], rz3, pk2(h3, h3)); aN3 = fmaf(nn.w, h3, aN3);
        }
        float2 srz = upk2(fadd2(fadd2(aRZ[0], aRZ[1]), fadd2(aRZ[2], aRZ[3])));
        float sN = (aN0 + aN1) + (aN2 + aN3);
        float rr = sigmoidf_(gR + bhr + srz.x);
        float uu = sigmoidf_(gZ + bhz + srz.y);
        float nn = tanhf_(gN + rr * (sN + bhn));
        float hnew = (1.0f - uu) * nn + uu * h_old;
        h_old = hnew;

        float* hw = p ? hbuf0 : hbuf1;
        uint32_t roff = p ? 0u : 4096u;
        hw[gr * 4 + bg] = hnew;
        st_cl32(ra0 + roff, hnew); st_cl32(ra1 + roff, hnew); st_cl32(ra2 + roff, hnew);
        cluster_sync_();
        p ^= 1;
    }
    {
        int bw = b0 + (int)r;
        g_hT[(size_t)bw * HDIM + tid] = hbuf0[tid * 4 + (int)r];
    }
}

// ============================================================
// origin #3: Encoder head: mu, logsigma, z, h0. grid=B (32).
// ============================================================
__global__ __launch_bounds__(256) void enc_head(
    const float* __restrict__ mu_w,  const float* __restrict__ mu_b,
    const float* __restrict__ ls_w,  const float* __restrict__ ls_b,
    const float* __restrict__ refc_w, const float* __restrict__ refc_b,
    const float* __restrict__ eps,   float* __restrict__ out)
{
    int b = blockIdx.x;
    int u = threadIdx.x;
    __shared__ float hT[HDIM];
    __shared__ float zv[ZDIM];
    hT[u] = g_hT[(size_t)b * HDIM + u];
    __syncthreads();
    if (u < ZDIM) {
        const float* mw = mu_w + u * HDIM;
        const float* lw = ls_w + u * HDIM;
        float am = mu_b[u], al = ls_b[u];
#pragma unroll 8
        for (int k = 0; k < HDIM; k++) { am += mw[k] * hT[k]; al += lw[k] * hT[k]; }
        out[BDIM * TDIM * DDIM + b * ZDIM + u] = am;
        out[BDIM * TDIM * DDIM + BDIM * ZDIM + b * ZDIM + u] = al;
        zv[u] = am + eps[b * ZDIM + u] * __expf(al);
    }
    __syncthreads();
    {
        float acc = refc_b[u];
        const float* rw = refc_w + u * ZDIM;
#pragma unroll 8
        for (int j = 0; j < ZDIM; j++) acc += rw[j] * zv[j];
        g_h0[(size_t)b * HDIM + u] = tanhf_(acc);
    }
}

// ============================================================
// Decoder GRU — proven R7/R13 structure. 32 clusters of 4 CTAs, 256 thr.
// ============================================================
#define DSM_WN  131072
#define DSM_H   196608
#define DSM_FCW 229376
#define DSM_TOT 230400
__global__ __launch_bounds__(256, 1) __cluster_dims__(4, 1, 1)
void dec_gru_cl(
    const float* __restrict__ bih_all, const float* __restrict__ bhh_all,
    const float* __restrict__ fcw_all, const float* __restrict__ fcb_all,
    float* __restrict__ out)
{
    extern __shared__ char smem_d[];
    float4* w_rz = (float4*)smem_d;
    float4* w_n  = (float4*)(smem_d + DSM_WN);
    float*  h_s  = (float*)(smem_d + DSM_H);     // [256][32]
    float*  fcw_s= (float*)(smem_d + DSM_FCW);
    __shared__ float wsum[8][8];

    int d = blockIdx.x >> 2;
    uint32_t r = ctarank_();
    int tid = threadIdx.x;
    int ul = tid >> 2, bg = tid & 3;
    int gr = (int)r * 64 + ul;

    {
        const float4* src_rz = g_Drz + (size_t)d * 128 * 256;
        for (int i = tid; i < 128 * 64; i += 256) {
            int k2 = i >> 6, uu = i & 63;
            w_rz[k2 * 64 + uu] = src_rz[(size_t)k2 * 256 + (int)r * 64 + uu];
        }
        const float4* src_n = g_Dn4 + (size_t)d * 64 * 256;
        for (int i = tid; i < 64 * 64; i += 256) {
            int k4 = i >> 6, uu = i & 63;
            w_n[k4 * 64 + uu] = src_n[(size_t)k4 * 256 + (int)r * 64 + uu];
        }
        fcw_s[tid] = fcw_all[d * HDIM + tid];
        for (int i = tid; i < 256 * 32; i += 256) {
            int uu = i >> 5, bb = i & 31;
            h_s[uu * 32 + bb] = g_h0[(size_t)bb * HDIM + uu];
        }
    }
    const float* bih = bih_all + d * G3;
    const float* bhh = bhh_all + d * G3;
    float br  = bih[gr] + bhh[gr];
    float bz  = bih[gr + HDIM] + bhh[gr + HDIM];
    float bni = bih[gr + 2 * HDIM];
    float bnh = bhh[gr + 2 * HDIM];
    float fcb = fcb_all[d];

    float hold[8];
#pragma unroll
    for (int bb = 0; bb < 8; bb++) hold[bb] = g_h0[(size_t)(bg * 8 + bb) * HDIM + gr];

    uint32_t hoff = s2u(&h_s[gr * 32 + bg * 8]);
    uint32_t ra0, ra1, ra2;
    {
        uint32_t tmp[3]; int nr = 0;
        for (uint32_t c = 0; c < 4; c++) if (c != r) tmp[nr++] = mapa_(hoff, c);
        ra0 = tmp[0]; ra1 = tmp[1]; ra2 = tmp[2];
    }
    __syncthreads();

    const float* gi_base = g_decGi + ((size_t)d * TDIM * G3) * BDIM + (size_t)gr * BDIM + bg * 8;

    for (int t = 0; t < TDIM; t++) {
        const float* gp = gi_base + (size_t)t * G3 * BDIM;
        float4 gR0 = *(const float4*)(gp);
        float4 gR1 = *(const float4*)(gp + 4);
        float4 gZ0 = *(const float4*)(gp + 256 * BDIM);
        float4 gZ1 = *(const float4*)(gp + 256 * BDIM + 4);
        float4 gN0 = *(const float4*)(gp + 512 * BDIM);
        float4 gN1 = *(const float4*)(gp + 512 * BDIM + 4);

        ull aR[4] = {0,0,0,0}, aZ[4] = {0,0,0,0}, aN[4] = {0,0,0,0};
#pragma unroll 8
        for (int k4 = 0; k4 < 64; k4++) {
            float4 rzA = w_rz[(2 * k4) * 64 + ul];
            float4 rzB = w_rz[(2 * k4 + 1) * 64 + ul];
            float4 nn  = w_n[k4 * 64 + ul];
            const ulonglong2* hp0 = (const ulonglong2*)&h_s[(k4 * 4 + 0) * 32 + bg * 8];
            const ulonglong2* hp1 = (const ulonglong2*)&h_s[(k4 * 4 + 1) * 32 + bg * 8];
            const ulonglong2* hp2 = (const ulonglong2*)&h_s[(k4 * 4 + 2) * 32 + bg * 8];
            const ulonglong2* hp3 = (const ulonglong2*)&h_s[(k4 * 4 + 3) * 32 + bg * 8];
            {
                ulonglong2 hA = hp0[0], hB = hp0[1];
                ull wr = pk2(rzA.x, rzA.x), wz = pk2(rzA.y, rzA.y), wn = pk2(nn.x, nn.x);
                ffma2(aR[0], wr, hA.x); ffma2(aR[1], wr, hA.y); ffma2(aR[2], wr, hB.x); ffma2(aR[3], wr, hB.y);
                ffma2(aZ[0], wz, hA.x); ffma2(aZ[1], wz, hA.y); ffma2(aZ[2], wz, hB.x); ffma2(aZ[3], wz, hB.y);
                ffma2(aN[0], wn, hA.x); ffma2(aN[1], wn, hA.y); ffma2(aN[2], wn, hB.x); ffma2(aN[3], wn, hB.y);
            }
            {
                ulonglong2 hA = hp1[0], hB = hp1[1];
                ull wr = pk2(rzA.z, rzA.z), wz = pk2(rzA.w, rzA.w), wn = pk2(nn.y, nn.y);
                ffma2(aR[0], wr, hA.x); ffma2(aR[1], wr, hA.y); ffma2(aR[2], wr, hB.x); ffma2(aR[3], wr, hB.y);
                ffma2(aZ[0], wz, hA.x); ffma2(aZ[1], wz, hA.y); ffma2(aZ[2], wz, hB.x); ffma2(aZ[3], wz, hB.y);
                ffma2(aN[0], wn, hA.x); ffma2(aN[1], wn, hA.y); ffma2(aN[2], wn, hB.x); ffma2(aN[3], wn, hB.y);
            }
            {
                ulonglong2 hA = hp2[0], hB = hp2[1];
                ull wr = pk2(rzB.x, rzB.x), wz = pk2(rzB.y, rzB.y), wn = pk2(nn.z, nn.z);
                ffma2(aR[0], wr, hA.x); ffma2(aR[1], wr, hA.y); ffma2(aR[2], wr, hB.x); ffma2(aR[3], wr, hB.y);
                ffma2(aZ[0], wz, hA.x); ffma2(aZ[1], wz, hA.y); ffma2(aZ[2], wz, hB.x); ffma2(aZ[3], wz, hB.y);
                ffma2(aN[0], wn, hA.x); ffma2(aN[1], wn, hA.y); ffma2(aN[2], wn, hB.x); ffma2(aN[3], wn, hB.y);
            }
            {
                ulonglong2 hA = hp3[0], hB = hp3[1];
                ull wr = pk2(rzB.z, rzB.z), wz = pk2(rzB.w, rzB.w), wn = pk2(nn.w, nn.w);
                ffma2(aR[0], wr, hA.x); ffma2(aR[1], wr, hA.y); ffma2(aR[2], wr, hB.x); ffma2(aR[3], wr, hB.y);
                ffma2(aZ[0], wz, hA.x); ffma2(aZ[1], wz, hA.y); ffma2(aZ[2], wz, hB.x); ffma2(aZ[3], wz, hB.y);
                ffma2(aN[0], wn, hA.x); ffma2(aN[1], wn, hA.y); ffma2(aN[2], wn, hB.x); ffma2(aN[3], wn, hB.y);
            }
        }

        float gR[8] = {gR0.x,gR0.y,gR0.z,gR0.w,gR1.x,gR1.y,gR1.z,gR1.w};
        float gZ[8] = {gZ0.x,gZ0.y,gZ0.z,gZ0.w,gZ1.x,gZ1.y,gZ1.z,gZ1.w};
        float gN[8] = {gN0.x,gN0.y,gN0.z,gN0.w,gN1.x,gN1.y,gN1.z,gN1.w};
        float hn[8];
#pragma unroll
        for (int p = 0; p < 4; p++) {
            float2 sR = upk2(aR[p]), sZ = upk2(aZ[p]), sN = upk2(aN[p]);
            float rA = sigmoidf_(gR[2*p]   + br + sR.x);
            float rB = sigmoidf_(gR[2*p+1] + br + sR.y);
            float uA = sigmoidf_(gZ[2*p]   + bz + sZ.x);
            float uB = sigmoidf_(gZ[2*p+1] + bz + sZ.y);
            float nA = tanhf_(gN[2*p]   + bni + rA * (sN.x + bnh));
            float nB = tanhf_(gN[2*p+1] + bni + rB * (sN.y + bnh));
            hn[2*p]   = (1.0f - uA) * nA + uA * hold[2*p];
            hn[2*p+1] = (1.0f - uB) * nB + uB * hold[2*p+1];
        }
#pragma unroll
        for (int bb = 0; bb < 8; bb++) hold[bb] = hn[bb];

        cluster_sync_();
        ull h01 = pk2(hn[0], hn[1]), h23 = pk2(hn[2], hn[3]);
        ull h45 = pk2(hn[4], hn[5]), h67 = pk2(hn[6], hn[7]);
        ull* lp = (ull*)&h_s[gr * 32 + bg * 8];
        lp[0] = h01; lp[1] = h23; lp[2] = h45; lp[3] = h67;
        st_cl64(ra0,      h01); st_cl64(ra0 + 8,  h23); st_cl64(ra0 + 16, h45); st_cl64(ra0 + 24, h67);
        st_cl64(ra1,      h01); st_cl64(ra1 + 8,  h23); st_cl64(ra1 + 16, h45); st_cl64(ra1 + 24, h67);
        st_cl64(ra2,      h01); st_cl64(ra2 + 8,  h23); st_cl64(ra2 + 16, h45); st_cl64(ra2 + 24, h67);
        cluster_sync_();

        {
            float4 ha = *(const float4*)&h_s[tid * 32 + (int)r * 8];
            float4 hb = *(const float4*)&h_s[tid * 32 + (int)r * 8 + 4];
            float pr[8] = {ha.x, ha.y, ha.z, ha.w, hb.x, hb.y, hb.z, hb.w};
            float fw = fcw_s[tid];
#pragma unroll
            for (int bb = 0; bb < 8; bb++) pr[bb] *= fw;
#pragma unroll
            for (int off = 16; off; off >>= 1) {
#pragma unroll
                for (int bb = 0; bb < 8; bb++)
                    pr[bb] += __shfl_xor_sync(0xffffffff, pr[bb], off);
            }
            if ((tid & 31) == 0) {
                int w = tid >> 5;
#pragma unroll
                for (int bb = 0; bb < 8; bb++) wsum[w][bb] = pr[bb];
            }
            __syncthreads();
            if (tid < 8) {
                float s = fcb;
#pragma unroll
                for (int w = 0; w < 8; w++) s += wsum[w][tid];
                int b = (int)r * 8 + tid;
                out[((size_t)b * TDIM + t) * DDIM + d] = s;
            }
        }
    }
}

// ============================================================
// launch — DAG; prep_decgi v2 in profiled slot #4
// ============================================================
extern "C" void kernel_launch(void* const* d_in, const int* in_sizes, int n_in,
                              void* d_out, int out_size)
{
    const float* x_past   = (const float*)d_in[0];
    const float* x_current= (const float*)d_in[1];
    const float* eps      = (const float*)d_in[2];
    const float* enc_Wih  = (const float*)d_in[3];
    const float* enc_bih  = (const float*)d_in[4];
    const float* enc_Whh  = (const float*)d_in[5];
    const float* enc_bhh  = (const float*)d_in[6];
    const float* enc_mu_w = (const float*)d_in[7];
    const float* enc_mu_b = (const float*)d_in[8];
    const float* enc_ls_w = (const float*)d_in[9];
    const float* enc_ls_b = (const float*)d_in[10];
    const float* refc_w   = (const float*)d_in[11];
    const float* refc_b   = (const float*)d_in[12];
    const float* Win      = (const float*)d_in[13];
    const float* h_Wih    = (const float*)d_in[14];
    const float* h_bih    = (const float*)d_in[15];
    const float* h_Whh    = (const float*)d_in[16];
    const float* h_bhh    = (const float*)d_in[17];
    const float* fc_w     = (const float*)d_in[18];
    const float* fc_b     = (const float*)d_in[19];
    float* out = (float*)d_out;

    static cudaStream_t s1 = nullptr, s2 = nullptr;
    static cudaEvent_t eF = nullptr, e1 = nullptr, e2 = nullptr;
    if (!s1) {
        cudaStreamCreateWithFlags(&s1, cudaStreamNonBlocking);
        cudaStreamCreateWithFlags(&s2, cudaStreamNonBlocking);
        cudaEventCreateWithFlags(&eF, cudaEventDisableTiming);
        cudaEventCreateWithFlags(&e1, cudaEventDisableTiming);
        cudaEventCreateWithFlags(&e2, cudaEventDisableTiming);
        cudaFuncSetAttribute(enc_gru_cl, cudaFuncAttributeMaxDynamicSharedMemorySize, ESM_TOT);
        cudaFuncSetAttribute(dec_gru_cl, cudaFuncAttributeMaxDynamicSharedMemorySize, DSM_TOT);
    }

    // fork side streams off the capture-origin stream
    cudaEventRecord(eF, 0);
    cudaStreamWaitEvent(s1, eF, 0);
    cudaStreamWaitEvent(s2, eF, 0);

    // origin: encoder chain
    prep_enc<<<2112, 256>>>(x_past, enc_Wih, enc_bih, enc_Whh);          // #1
    // s1: decoder input-gate chain
    prep_wcomb<<<DDIM * 96, 256, 0, s1>>>(Win, h_Wih);                   // #2
    enc_gru_cl<<<32, 256, ESM_TOT>>>(enc_bhh);                           // #3
    prep_decgi<<<192, 256, 0, s1>>>(x_past, x_current);                  // #4 (profiled)
    // s2: decoder weight transpose
    prep_dtrans<<<2048, 256, 0, s2>>>(h_Whh);                            // #5
    enc_head<<<BDIM, 256>>>(enc_mu_w, enc_mu_b, enc_ls_w, enc_ls_b,
                            refc_w, refc_b, eps, out);                   // #6

    // join
    cudaEventRecord(e1, s1);
    cudaEventRecord(e2, s2);
    cudaStreamWaitEvent(0, e1, 0);
    cudaStreamWaitEvent(0, e2, 0);
    dec_gru_cl<<<DDIM * 4, 256, DSM_TOT>>>(h_bih, h_bhh, fc_w, fc_b, out); // #7
}